// round 4
// baseline (speedup 1.0000x reference)
#include <cuda_runtime.h>

#define BB   16
#define NN   512
#define DIN  256
#define DD   64
#define EE   32
#define MAXDIST 50

typedef unsigned long long ull;

__device__ __forceinline__ void fma2(ull& d, ull a, ull b) {
    asm("fma.rn.f32x2 %0, %1, %2, %0;" : "+l"(d) : "l"(a), "l"(b));
}
__device__ __forceinline__ ull dup2(float x) {
    unsigned u = __float_as_uint(x); ull d;
    asm("mov.b64 %0, {%1, %1};" : "=l"(d) : "r"(u));
    return d;
}
__device__ __forceinline__ float2 unpk(ull u) {
    unsigned lo, hi;
    asm("mov.b64 {%0, %1}, %2;" : "=r"(lo), "=r"(hi) : "l"(u));
    return make_float2(__uint_as_float(lo), __uint_as_float(hi));
}

__device__ float g_qT[BB*DD*NN];   // per batch: [d][n]
__device__ float g_kT[BB*DD*NN];   // per batch: [d][n]
__device__ float g_v [BB*NN*DD];   // row-major [n][d]
__device__ float g_rel[MAXDIST+1]; // 0.125 * sigmoid(...)

// ============================================================
// Kernel 1: xp = x@Wp+bp ; q,k,v = xp@W{q,k,v}+b (FFMA2)
// ============================================================
__global__ __launch_bounds__(256) void qkv_kernel(
    const float* __restrict__ x,
    const float* __restrict__ Wp, const float* __restrict__ bp,
    const float* __restrict__ Wq, const float* __restrict__ bq,
    const float* __restrict__ Wk, const float* __restrict__ bk,
    const float* __restrict__ Wv, const float* __restrict__ bv,
    const float* __restrict__ Eemb, const float* __restrict__ Wr1,
    const float* __restrict__ br1,  const float* __restrict__ Wr2) {
    __shared__ float bufA[64*68];
    __shared__ float bufB[64*68];
    const int tid = threadIdx.x;
    const int ty = tid >> 4, tx = tid & 15;
    const int row0 = blockIdx.x * 64;
    const int b = row0 >> 9;
    const int n0 = row0 & 511;

    if (blockIdx.x == 0 && tid <= MAXDIST) {
        float e[EE];
#pragma unroll
        for (int c = 0; c < EE; c++) e[c] = Eemb[tid*EE + c];
        float w = 0.f;
#pragma unroll
        for (int j = 0; j < 16; j++) {
            float h = br1[j];
#pragma unroll
            for (int c = 0; c < EE; c++) h = fmaf(e[c], Wr1[c*16 + j], h);
            h = fmaxf(h, 0.f);
            w = fmaf(h, Wr2[j], w);
        }
        g_rel[tid] = 0.125f / (1.f + __expf(-w));
    }

    const int fi = tid >> 4;        // float4 row index helper
    const int ff = tid & 15;        // float4 col index

    // --- xp = x @ Wp (float4 prefetch) ---
    float4 ra4[4], rb4[4];
#pragma unroll
    for (int j = 0; j < 4; j++) {
        int i = fi + j*16;
        ra4[j] = *(const float4*)&x[(row0 + i)*DIN + ff*4];
        rb4[j] = *(const float4*)&Wp[i*DD + ff*4];
    }
    ull acc2[2][4];
#pragma unroll
    for (int p = 0; p < 2; p++)
#pragma unroll
        for (int c = 0; c < 4; c++) acc2[p][c] = 0ULL;

    for (int kc = 0; kc < 4; kc++) {
#pragma unroll
        for (int j = 0; j < 4; j++) {
            int i = fi + j*16;
            // x chunk transposed (scalar scatter)
            bufA[(ff*4 + 0)*68 + i] = ra4[j].x;
            bufA[(ff*4 + 1)*68 + i] = ra4[j].y;
            bufA[(ff*4 + 2)*68 + i] = ra4[j].z;
            bufA[(ff*4 + 3)*68 + i] = ra4[j].w;
            *(float4*)&bufB[i*68 + ff*4] = rb4[j];
        }
        __syncthreads();
        if (kc < 3) {
#pragma unroll
            for (int j = 0; j < 4; j++) {
                int i = fi + j*16;
                ra4[j] = *(const float4*)&x[(row0 + i)*DIN + (kc+1)*64 + ff*4];
                rb4[j] = *(const float4*)&Wp[((kc+1)*64 + i)*DD + ff*4];
            }
        }
#pragma unroll 8
        for (int kk = 0; kk < 64; kk++) {
            ulonglong2 a = *(const ulonglong2*)&bufA[kk*68 + ty*4];
            float4 bw = *(const float4*)&bufB[kk*68 + tx*4];
            ull b0 = dup2(bw.x), b1 = dup2(bw.y), b2 = dup2(bw.z), b3 = dup2(bw.w);
            fma2(acc2[0][0], a.x, b0); fma2(acc2[0][1], a.x, b1);
            fma2(acc2[0][2], a.x, b2); fma2(acc2[0][3], a.x, b3);
            fma2(acc2[1][0], a.y, b0); fma2(acc2[1][1], a.y, b1);
            fma2(acc2[1][2], a.y, b2); fma2(acc2[1][3], a.y, b3);
        }
        __syncthreads();
    }
#pragma unroll
    for (int c = 0; c < 4; c++) {
        float2 p0 = unpk(acc2[0][c]), p1 = unpk(acc2[1][c]);
        float bias = bp[tx*4 + c];
        float4 v4 = {p0.x + bias, p0.y + bias, p1.x + bias, p1.y + bias};
        *(float4*)&bufA[(tx*4 + c)*68 + ty*4] = v4;
    }
    __syncthreads();

    const float* Ws[3] = {Wq, Wk, Wv};
    const float* bs[3] = {bq, bk, bv};
    for (int t = 0; t < 3; t++) {
#pragma unroll
        for (int j = 0; j < 4; j++) {
            int i = fi + j*16;
            *(float4*)&bufB[i*68 + ff*4] = *(const float4*)&Ws[t][i*DD + ff*4];
        }
        __syncthreads();
        ull o2[2][4];
#pragma unroll
        for (int p = 0; p < 2; p++)
#pragma unroll
            for (int c = 0; c < 4; c++) o2[p][c] = 0ULL;
#pragma unroll 8
        for (int kk = 0; kk < 64; kk++) {
            ulonglong2 a = *(const ulonglong2*)&bufA[kk*68 + ty*4];
            float4 bw = *(const float4*)&bufB[kk*68 + tx*4];
            ull b0 = dup2(bw.x), b1 = dup2(bw.y), b2 = dup2(bw.z), b3 = dup2(bw.w);
            fma2(o2[0][0], a.x, b0); fma2(o2[0][1], a.x, b1);
            fma2(o2[0][2], a.x, b2); fma2(o2[0][3], a.x, b3);
            fma2(o2[1][0], a.y, b0); fma2(o2[1][1], a.y, b1);
            fma2(o2[1][2], a.y, b2); fma2(o2[1][3], a.y, b3);
        }
        if (t == 2) {
            float2 u[2][4];
#pragma unroll
            for (int p = 0; p < 2; p++)
#pragma unroll
                for (int c = 0; c < 4; c++) u[p][c] = unpk(o2[p][c]);
            float4 bias = *(const float4*)&bs[2][tx*4];
#pragma unroll
            for (int r = 0; r < 4; r++) {
                float4 v4;
                float2* up = u[r >> 1];
                if (r & 1) v4 = make_float4(up[0].y + bias.x, up[1].y + bias.y, up[2].y + bias.z, up[3].y + bias.w);
                else       v4 = make_float4(up[0].x + bias.x, up[1].x + bias.y, up[2].x + bias.z, up[3].x + bias.w);
                *(float4*)&g_v[(row0 + ty*4 + r)*DD + tx*4] = v4;
            }
        } else {
            float* dst = (t == 0) ? g_qT : g_kT;
#pragma unroll
            for (int c = 0; c < 4; c++) {
                float2 p0 = unpk(o2[0][c]), p1 = unpk(o2[1][c]);
                float bias = bs[t][tx*4 + c];
                float4 v4 = {p0.x + bias, p0.y + bias, p1.x + bias, p1.y + bias};
                *(float4*)&dst[b*DD*NN + (tx*4 + c)*NN + n0 + ty*4] = v4;
            }
        }
        __syncthreads();
    }
}

// ============================================================
// Kernel 2: fused attention + FFN + LN + head. 512 threads.
// ============================================================
#define S_STRIDE 516
#define R1_OFF   33024
#define R2_OFF   49664
#define REL_OFF  54016
#define RK_OFF   54080
#define INV_OFF  54592
#define SMEM_FLOATS 54656
#define SMEM_BYTES  (SMEM_FLOATS*4)

__global__ __launch_bounds__(512) void attn_kernel(
    const int* __restrict__ ranks,
    const float* __restrict__ Wf1, const float* __restrict__ bf1,
    const float* __restrict__ Wf2, const float* __restrict__ bf2,
    const float* __restrict__ ln_g, const float* __restrict__ ln_b,
    const float* __restrict__ Ws1, const float* __restrict__ bs1,
    const float* __restrict__ Ws2, const float* __restrict__ bs2,
    float* __restrict__ out) {
    extern __shared__ float sm[];
    float* S    = sm;
    float* R1   = sm + R1_OFF;
    float* R2   = sm + R2_OFF;
    float* rel  = sm + REL_OFF;
    int*   rk   = (int*)(sm + RK_OFF);
    float* invs = sm + INV_OFF;

    const int tid = threadIdx.x;
    const int b = blockIdx.y;
    const int q0 = blockIdx.x * 64;
    const int base = b * NN;
    const int bT = b * DD * NN;

    if (tid <= MAXDIST) rel[tid] = g_rel[tid];
    for (int m = tid; m < NN; m += 512) rk[m] = ranks[base + m];
    // qT staging (float4): 64x64
#pragma unroll
    for (int j = 0; j < 2; j++) {
        int idx = tid + j*512;
        int d = idx >> 4, f = idx & 15;
        *(float4*)&R2[d*68 + f*4] = *(const float4*)&g_qT[bT + d*NN + q0 + f*4];
    }
    __syncthreads();

    // ---- Phase 1: S = exp-arg = (QK^T)*rel8  (8 rows x 4 keys/thread, FFMA2) ----
    {
        const int ty = tid >> 6;
        const int tx = tid & 63;
        int ri[8];
#pragma unroll
        for (int rr = 0; rr < 8; rr++) ri[rr] = rk[q0 + ty*8 + rr];

        for (int kc = 0; kc < 2; kc++) {
            const int k0 = kc * 256;
            // stage kT chunk [64][256] as float4
#pragma unroll
            for (int j = 0; j < 8; j++) {
                int idx = tid + j*512;
                int d = idx >> 6, f = idx & 63;
                *(float4*)&R1[d*260 + f*4] = *(const float4*)&g_kT[bT + d*NN + k0 + f*4];
            }
            __syncthreads();
            ull acc2[4][4];
#pragma unroll
            for (int p = 0; p < 4; p++)
#pragma unroll
                for (int c = 0; c < 4; c++) acc2[p][c] = 0ULL;
#pragma unroll 4
            for (int d = 0; d < 64; d++) {
                ulonglong2 a01 = *(const ulonglong2*)&R2[d*68 + ty*8];
                ulonglong2 a23 = *(const ulonglong2*)&R2[d*68 + ty*8 + 4];
                float4 kb = *(const float4*)&R1[d*260 + tx*4];
                ull b0 = dup2(kb.x), b1 = dup2(kb.y), b2 = dup2(kb.z), b3 = dup2(kb.w);
                fma2(acc2[0][0], a01.x, b0); fma2(acc2[0][1], a01.x, b1);
                fma2(acc2[0][2], a01.x, b2); fma2(acc2[0][3], a01.x, b3);
                fma2(acc2[1][0], a01.y, b0); fma2(acc2[1][1], a01.y, b1);
                fma2(acc2[1][2], a01.y, b2); fma2(acc2[1][3], a01.y, b3);
                fma2(acc2[2][0], a23.x, b0); fma2(acc2[2][1], a23.x, b1);
                fma2(acc2[2][2], a23.x, b2); fma2(acc2[2][3], a23.x, b3);
                fma2(acc2[3][0], a23.y, b0); fma2(acc2[3][1], a23.y, b1);
                fma2(acc2[3][2], a23.y, b2); fma2(acc2[3][3], a23.y, b3);
            }
            int rkc[4];
#pragma unroll
            for (int c = 0; c < 4; c++) rkc[c] = rk[k0 + tx*4 + c];
#pragma unroll
            for (int p = 0; p < 4; p++) {
                float4 olo, ohi;
                float* plo = (float*)&olo;
                float* phi = (float*)&ohi;
                int rlo = ri[2*p], rhi = ri[2*p + 1];
#pragma unroll
                for (int c = 0; c < 4; c++) {
                    float2 u = unpk(acc2[p][c]);
                    int d0 = rlo - rkc[c]; if (d0 < 0) d0 = -d0; if (d0 > MAXDIST) d0 = MAXDIST;
                    int d1 = rhi - rkc[c]; if (d1 < 0) d1 = -d1; if (d1 > MAXDIST) d1 = MAXDIST;
                    plo[c] = u.x * rel[d0];
                    phi[c] = u.y * rel[d1];
                }
                *(float4*)&S[(ty*8 + 2*p    )*S_STRIDE + k0 + tx*4] = olo;
                *(float4*)&S[(ty*8 + 2*p + 1)*S_STRIDE + k0 + tx*4] = ohi;
            }
            __syncthreads();
        }
    }

    // ---- Phase 2: single-pass exp + sum (no max subtraction; scores are O(5)) ----
    {
        const int warp = tid >> 5, lane = tid & 31;
#pragma unroll
        for (int rr = 0; rr < 4; rr++) {
            float* Sr = S + (warp*4 + rr)*S_STRIDE;
            float sum = 0.f;
#pragma unroll
            for (int j = 0; j < 4; j++) {
                float4 vv = *(const float4*)&Sr[lane*4 + j*128];
                vv.x = __expf(vv.x); vv.y = __expf(vv.y);
                vv.z = __expf(vv.z); vv.w = __expf(vv.w);
                *(float4*)&Sr[lane*4 + j*128] = vv;
                sum += (vv.x + vv.y) + (vv.z + vv.w);
            }
#pragma unroll
            for (int o = 16; o >= 1; o >>= 1) sum += __shfl_xor_sync(0xffffffffu, sum, o);
            if (lane == 0) invs[warp*4 + rr] = 1.f / sum;
        }
    }
    __syncthreads();

    // ---- Phase 3: AO = (exp-P)@V * inv, split-K 4 groups x 128 threads ----
    {
        const int g3   = tid >> 7;
        const int t3   = tid & 127;
        const int rowg = t3 >> 3;
        const int colg = t3 & 7;
        ull acc2[4][4];
#pragma unroll
        for (int r = 0; r < 4; r++)
#pragma unroll
            for (int c = 0; c < 4; c++) acc2[r][c] = 0ULL;

        for (int rnd = 0; rnd < 2; rnd++) {
            // stage v chunk [256][64] as float4
#pragma unroll
            for (int j = 0; j < 8; j++) {
                int idx = tid + j*512;
                int key = idx >> 4, f = idx & 15;
                *(float4*)&R1[key*64 + f*4] = *(const float4*)&g_v[(base + rnd*256 + key)*DD + f*4];
            }
            __syncthreads();
            const int kl0 = g3 * 64;
            const int kg0 = rnd*256 + kl0;
#pragma unroll 2
            for (int kl = 0; kl < 64; kl += 4) {
                const int key = kg0 + kl;
                float4 p0 = *(const float4*)&S[(rowg*4 + 0)*S_STRIDE + key];
                float4 p1 = *(const float4*)&S[(rowg*4 + 1)*S_STRIDE + key];
                float4 p2 = *(const float4*)&S[(rowg*4 + 2)*S_STRIDE + key];
                float4 p3 = *(const float4*)&S[(rowg*4 + 3)*S_STRIDE + key];
                const float* pp0 = (const float*)&p0;
                const float* pp1 = (const float*)&p1;
                const float* pp2 = (const float*)&p2;
                const float* pp3 = (const float*)&p3;
#pragma unroll
                for (int j = 0; j < 4; j++) {
                    ulonglong2 v0 = *(const ulonglong2*)&R1[(kl0 + kl + j)*64 + colg*8];
                    ulonglong2 v1 = *(const ulonglong2*)&R1[(kl0 + kl + j)*64 + colg*8 + 4];
                    ull pa0 = dup2(pp0[j]);
                    ull pa1 = dup2(pp1[j]);
                    ull pa2 = dup2(pp2[j]);
                    ull pa3 = dup2(pp3[j]);
                    fma2(acc2[0][0], pa0, v0.x); fma2(acc2[0][1], pa0, v0.y);
                    fma2(acc2[0][2], pa0, v1.x); fma2(acc2[0][3], pa0, v1.y);
                    fma2(acc2[1][0], pa1, v0.x); fma2(acc2[1][1], pa1, v0.y);
                    fma2(acc2[1][2], pa1, v1.x); fma2(acc2[1][3], pa1, v1.y);
                    fma2(acc2[2][0], pa2, v0.x); fma2(acc2[2][1], pa2, v0.y);
                    fma2(acc2[2][2], pa2, v1.x); fma2(acc2[2][3], pa2, v1.y);
                    fma2(acc2[3][0], pa3, v0.x); fma2(acc2[3][1], pa3, v0.y);
                    fma2(acc2[3][2], pa3, v1.x); fma2(acc2[3][3], pa3, v1.y);
                }
            }
            __syncthreads();
        }
        float po[4][8];
#pragma unroll
        for (int r = 0; r < 4; r++)
#pragma unroll
            for (int c = 0; c < 4; c++) {
                float2 u = unpk(acc2[r][c]);
                po[r][2*c] = u.x; po[r][2*c + 1] = u.y;
            }
        if (g3 > 0) {
            float* part = S + (g3 - 1)*4096;
#pragma unroll
            for (int r = 0; r < 4; r++) {
                *(float4*)&part[(rowg*4 + r)*64 + colg*8]     = *(float4*)&po[r][0];
                *(float4*)&part[(rowg*4 + r)*64 + colg*8 + 4] = *(float4*)&po[r][4];
            }
        }
        __syncthreads();
        if (g3 == 0) {
#pragma unroll
            for (int gg = 0; gg < 3; gg++) {
                float* part = S + gg*4096;
#pragma unroll
                for (int r = 0; r < 4; r++) {
                    float4 q0v = *(const float4*)&part[(rowg*4 + r)*64 + colg*8];
                    float4 q1v = *(const float4*)&part[(rowg*4 + r)*64 + colg*8 + 4];
                    po[r][0] += q0v.x; po[r][1] += q0v.y; po[r][2] += q0v.z; po[r][3] += q0v.w;
                    po[r][4] += q1v.x; po[r][5] += q1v.y; po[r][6] += q1v.z; po[r][7] += q1v.w;
                }
            }
            float iv[4];
#pragma unroll
            for (int r = 0; r < 4; r++) iv[r] = invs[rowg*4 + r];
#pragma unroll
            for (int c = 0; c < 8; c++) {
                float4 v4 = {po[0][c]*iv[0], po[1][c]*iv[1], po[2][c]*iv[2], po[3][c]*iv[3]};
                *(float4*)&R1[(colg*8 + c)*68 + rowg*4] = v4;
            }
        } else {
            // stage w1 = Wf1 (float4) by groups 1..3
            float* w1 = R1 + 4352;
            for (int j = (g3 - 1)*128 + t3; j < 2048; j += 384)
                *(float4*)&w1[j*4] = *(const float4*)&Wf1[j*4];
        }
    }
    __syncthreads();

    // ---- Phase 4a: h1 = relu(ao@Wf1+bf1) (64x128), FFMA2 ----
    {
        const float* w1 = R1 + 4352;
        const int ty = tid >> 5, tx = tid & 31;
        ull acc2[2][4];
#pragma unroll
        for (int p = 0; p < 2; p++)
#pragma unroll
            for (int c = 0; c < 4; c++) acc2[p][c] = 0ULL;
#pragma unroll 4
        for (int kk = 0; kk < 64; kk++) {
            ulonglong2 a = *(const ulonglong2*)&R1[kk*68 + ty*4];
            float4 bw = *(const float4*)&w1[kk*128 + tx*4];
            ull b0 = dup2(bw.x), b1 = dup2(bw.y), b2 = dup2(bw.z), b3 = dup2(bw.w);
            fma2(acc2[0][0], a.x, b0); fma2(acc2[0][1], a.x, b1);
            fma2(acc2[0][2], a.x, b2); fma2(acc2[0][3], a.x, b3);
            fma2(acc2[1][0], a.y, b0); fma2(acc2[1][1], a.y, b1);
            fma2(acc2[1][2], a.y, b2); fma2(acc2[1][3], a.y, b3);
        }
        __syncthreads();
#pragma unroll
        for (int c = 0; c < 4; c++) {
            float bias = bf1[tx*4 + c];
            float2 u0 = unpk(acc2[0][c]), u1 = unpk(acc2[1][c]);
            float4 v4 = {fmaxf(u0.x + bias, 0.f), fmaxf(u0.y + bias, 0.f),
                         fmaxf(u1.x + bias, 0.f), fmaxf(u1.y + bias, 0.f)};
            *(float4*)&S[(tx*4 + c)*68 + ty*4] = v4;
        }
#pragma unroll
        for (int j = 0; j < 4; j++) {
            int f = tid + j*512;
            *(float4*)&R1[f*4] = *(const float4*)&Wf2[f*4];
        }
    }
    __syncthreads();

    // ---- Phase 4b: h2 = h1@Wf2+bf2, LayerNorm, FFMA2 ----
    {
        const int ty = tid >> 5, tx = tid & 31;
        ull acc2[2][2];
        acc2[0][0] = acc2[0][1] = acc2[1][0] = acc2[1][1] = 0ULL;
#pragma unroll 4
        for (int kk = 0; kk < 128; kk++) {
            ulonglong2 a = *(const ulonglong2*)&S[kk*68 + ty*4];
            float2 bw = *(const float2*)&R1[kk*64 + tx*2];
            ull b0 = dup2(bw.x), b1 = dup2(bw.y);
            fma2(acc2[0][0], a.x, b0); fma2(acc2[0][1], a.x, b1);
            fma2(acc2[1][0], a.y, b0); fma2(acc2[1][1], a.y, b1);
        }
        __syncthreads();
        float h2[4][2];
        {
            float2 u00 = unpk(acc2[0][0]), u01 = unpk(acc2[0][1]);
            float2 u10 = unpk(acc2[1][0]), u11 = unpk(acc2[1][1]);
            h2[0][0] = u00.x; h2[0][1] = u01.x;
            h2[1][0] = u00.y; h2[1][1] = u01.y;
            h2[2][0] = u10.x; h2[2][1] = u11.x;
            h2[3][0] = u10.y; h2[3][1] = u11.y;
        }
        float b0 = bf2[tx*2], b1 = bf2[tx*2 + 1];
        float g0v = ln_g[tx*2], g1v = ln_g[tx*2 + 1];
        float be0 = ln_b[tx*2], be1 = ln_b[tx*2 + 1];
#pragma unroll
        for (int r = 0; r < 4; r++) {
            float e0 = h2[r][0] + b0, e1 = h2[r][1] + b1;
            float s  = e0 + e1;
            float s2 = e0*e0 + e1*e1;
#pragma unroll
            for (int o = 16; o >= 1; o >>= 1) {
                s  += __shfl_xor_sync(0xffffffffu, s,  o);
                s2 += __shfl_xor_sync(0xffffffffu, s2, o);
            }
            float mu = s * (1.f/64.f);
            float var = s2 * (1.f/64.f) - mu*mu;
            float inv = rsqrtf(var + 1e-5f);
            R2[(tx*2 + 0)*68 + ty*4 + r] = (e0 - mu)*inv*g0v + be0;
            R2[(tx*2 + 1)*68 + ty*4 + r] = (e1 - mu)*inv*g1v + be1;
        }
    }
    {
        if (tid < 512) {
            *(float4*)&R1[tid*4] = *(const float4*)&Ws1[tid*4];
        }
        if (tid < 8) *(float4*)&R1[2048 + tid*4] = *(const float4*)&Ws2[tid*4];
    }
    __syncthreads();

    // ---- Phase 4c: head (threads 0..255) ----
    if (tid < 256) {
        const int ty = tid >> 4, tx = tid & 15;
        float s1[4][2];
#pragma unroll
        for (int r = 0; r < 4; r++) { s1[r][0] = 0.f; s1[r][1] = 0.f; }
#pragma unroll 4
        for (int kk = 0; kk < 64; kk++) {
            float4 a = *(const float4*)&R2[kk*68 + ty*4];
            float w0 = R1[kk*32 + tx*2], w1b = R1[kk*32 + tx*2 + 1];
            s1[0][0] = fmaf(a.x, w0, s1[0][0]); s1[0][1] = fmaf(a.x, w1b, s1[0][1]);
            s1[1][0] = fmaf(a.y, w0, s1[1][0]); s1[1][1] = fmaf(a.y, w1b, s1[1][1]);
            s1[2][0] = fmaf(a.z, w0, s1[2][0]); s1[2][1] = fmaf(a.z, w1b, s1[2][1]);
            s1[3][0] = fmaf(a.w, w0, s1[3][0]); s1[3][1] = fmaf(a.w, w1b, s1[3][1]);
        }
        float w2a = R1[2048 + tx*2], w2b = R1[2048 + tx*2 + 1];
        float ba = bs1[tx*2], bb = bs1[tx*2 + 1];
        float bs2v = bs2[0];
#pragma unroll
        for (int r = 0; r < 4; r++) {
            float pa = fmaxf(s1[r][0] + ba, 0.f);
            float pb = fmaxf(s1[r][1] + bb, 0.f);
            float p = pa*w2a + pb*w2b;
#pragma unroll
            for (int o = 8; o >= 1; o >>= 1) p += __shfl_xor_sync(0xffffffffu, p, o, 16);
            if (tx == 0) {
                float z = p + bs2v;
                out[base + q0 + ty*4 + r] = 1.f / (1.f + __expf(-z));
            }
        }
    }
}

// ============================================================
extern "C" void kernel_launch(void* const* d_in, const int* in_sizes, int n_in,
                              void* d_out, int out_size) {
    const float* x     = (const float*)d_in[0];
    const int*   ranks = (const int*)  d_in[1];
    const float* Wp    = (const float*)d_in[2];
    const float* bp    = (const float*)d_in[3];
    const float* Wq    = (const float*)d_in[4];
    const float* bq    = (const float*)d_in[5];
    const float* Wk    = (const float*)d_in[6];
    const float* bk    = (const float*)d_in[7];
    const float* Wv    = (const float*)d_in[8];
    const float* bv    = (const float*)d_in[9];
    const float* Eemb  = (const float*)d_in[10];
    const float* Wr1   = (const float*)d_in[11];
    const float* br1   = (const float*)d_in[12];
    const float* Wr2   = (const float*)d_in[13];
    const float* Wf1   = (const float*)d_in[14];
    const float* bf1   = (const float*)d_in[15];
    const float* Wf2   = (const float*)d_in[16];
    const float* bf2   = (const float*)d_in[17];
    const float* ln_g  = (const float*)d_in[18];
    const float* ln_b  = (const float*)d_in[19];
    const float* Ws1   = (const float*)d_in[20];
    const float* bs1   = (const float*)d_in[21];
    const float* Ws2   = (const float*)d_in[22];
    const float* bs2   = (const float*)d_in[23];
    float* out = (float*)d_out;

    cudaFuncSetAttribute(attn_kernel, cudaFuncAttributeMaxDynamicSharedMemorySize, SMEM_BYTES);

    qkv_kernel<<<BB*NN/64, 256>>>(x, Wp, bp, Wq, bq, Wk, bk, Wv, bv,
                                  Eemb, Wr1, br1, Wr2);
    dim3 grid(NN/64, BB);
    attn_kernel<<<grid, 512, SMEM_BYTES>>>(ranks, Wf1, bf1, Wf2, bf2,
                                           ln_g, ln_b, Ws1, bs1, Ws2, bs2, out);
}

// round 6
// speedup vs baseline: 1.0329x; 1.0329x over previous
#include <cuda_runtime.h>

#define BB   16
#define NN   512
#define DIN  256
#define DD   64
#define EE   32
#define MAXDIST 50

typedef unsigned long long ull;

__device__ __forceinline__ void fma2(ull& d, ull a, ull b) {
    asm("fma.rn.f32x2 %0, %1, %2, %0;" : "+l"(d) : "l"(a), "l"(b));
}
__device__ __forceinline__ ull dup2(float x) {
    unsigned u = __float_as_uint(x); ull d;
    asm("mov.b64 %0, {%1, %1};" : "=l"(d) : "r"(u));
    return d;
}
__device__ __forceinline__ float2 unpk(ull u) {
    unsigned lo, hi;
    asm("mov.b64 {%0, %1}, %2;" : "=r"(lo), "=r"(hi) : "l"(u));
    return make_float2(__uint_as_float(lo), __uint_as_float(hi));
}
__device__ __forceinline__ float ex2(float x) {
    float r;
    asm("ex2.approx.f32 %0, %1;" : "=f"(r) : "f"(x));
    return r;
}

__device__ float g_qT[BB*DD*NN];   // per batch: [d][n]
__device__ float g_kT[BB*DD*NN];   // per batch: [d][n]
__device__ float g_v [BB*NN*DD];   // row-major [n][d]
__device__ float g_rel[MAXDIST+1]; // 0.125 * log2(e) * sigmoid(...)

// ============================================================
// Kernel 1: xp = x@Wp+bp ; q,k,v = xp@W{q,k,v}+b (FFMA2)
// ============================================================
__global__ __launch_bounds__(256) void qkv_kernel(
    const float* __restrict__ x,
    const float* __restrict__ Wp, const float* __restrict__ bp,
    const float* __restrict__ Wq, const float* __restrict__ bq,
    const float* __restrict__ Wk, const float* __restrict__ bk,
    const float* __restrict__ Wv, const float* __restrict__ bv,
    const float* __restrict__ Eemb, const float* __restrict__ Wr1,
    const float* __restrict__ br1,  const float* __restrict__ Wr2) {
    __shared__ float bufA[64*68];
    __shared__ float bufB[64*68];
    const int tid = threadIdx.x;
    const int ty = tid >> 4, tx = tid & 15;
    const int row0 = blockIdx.x * 64;
    const int b = row0 >> 9;
    const int n0 = row0 & 511;

    if (blockIdx.x == 0 && tid <= MAXDIST) {
        float e[EE];
#pragma unroll
        for (int c = 0; c < EE; c++) e[c] = Eemb[tid*EE + c];
        float w = 0.f;
#pragma unroll
        for (int j = 0; j < 16; j++) {
            float h = br1[j];
#pragma unroll
            for (int c = 0; c < EE; c++) h = fmaf(e[c], Wr1[c*16 + j], h);
            h = fmaxf(h, 0.f);
            w = fmaf(h, Wr2[j], w);
        }
        // 0.125 * log2(e) * sigmoid(w)
        g_rel[tid] = 0.18033688011112042f / (1.f + __expf(-w));
    }

    const int fi = tid >> 4;
    const int ff = tid & 15;

    float4 ra4[4], rb4[4];
#pragma unroll
    for (int j = 0; j < 4; j++) {
        int i = fi + j*16;
        ra4[j] = *(const float4*)&x[(row0 + i)*DIN + ff*4];
        rb4[j] = *(const float4*)&Wp[i*DD + ff*4];
    }
    ull acc2[2][4];
#pragma unroll
    for (int p = 0; p < 2; p++)
#pragma unroll
        for (int c = 0; c < 4; c++) acc2[p][c] = 0ULL;

    for (int kc = 0; kc < 4; kc++) {
#pragma unroll
        for (int j = 0; j < 4; j++) {
            int i = fi + j*16;
            bufA[(ff*4 + 0)*68 + i] = ra4[j].x;
            bufA[(ff*4 + 1)*68 + i] = ra4[j].y;
            bufA[(ff*4 + 2)*68 + i] = ra4[j].z;
            bufA[(ff*4 + 3)*68 + i] = ra4[j].w;
            *(float4*)&bufB[i*68 + ff*4] = rb4[j];
        }
        __syncthreads();
        if (kc < 3) {
#pragma unroll
            for (int j = 0; j < 4; j++) {
                int i = fi + j*16;
                ra4[j] = *(const float4*)&x[(row0 + i)*DIN + (kc+1)*64 + ff*4];
                rb4[j] = *(const float4*)&Wp[((kc+1)*64 + i)*DD + ff*4];
            }
        }
#pragma unroll 8
        for (int kk = 0; kk < 64; kk++) {
            ulonglong2 a = *(const ulonglong2*)&bufA[kk*68 + ty*4];
            float4 bw = *(const float4*)&bufB[kk*68 + tx*4];
            ull b0 = dup2(bw.x), b1 = dup2(bw.y), b2 = dup2(bw.z), b3 = dup2(bw.w);
            fma2(acc2[0][0], a.x, b0); fma2(acc2[0][1], a.x, b1);
            fma2(acc2[0][2], a.x, b2); fma2(acc2[0][3], a.x, b3);
            fma2(acc2[1][0], a.y, b0); fma2(acc2[1][1], a.y, b1);
            fma2(acc2[1][2], a.y, b2); fma2(acc2[1][3], a.y, b3);
        }
        __syncthreads();
    }
#pragma unroll
    for (int c = 0; c < 4; c++) {
        float2 p0 = unpk(acc2[0][c]), p1 = unpk(acc2[1][c]);
        float bias = bp[tx*4 + c];
        float4 v4 = {p0.x + bias, p0.y + bias, p1.x + bias, p1.y + bias};
        *(float4*)&bufA[(tx*4 + c)*68 + ty*4] = v4;
    }
    __syncthreads();

    const float* Ws[3] = {Wq, Wk, Wv};
    const float* bs[3] = {bq, bk, bv};
    for (int t = 0; t < 3; t++) {
#pragma unroll
        for (int j = 0; j < 4; j++) {
            int i = fi + j*16;
            *(float4*)&bufB[i*68 + ff*4] = *(const float4*)&Ws[t][i*DD + ff*4];
        }
        __syncthreads();
        ull o2[2][4];
#pragma unroll
        for (int p = 0; p < 2; p++)
#pragma unroll
            for (int c = 0; c < 4; c++) o2[p][c] = 0ULL;
#pragma unroll 8
        for (int kk = 0; kk < 64; kk++) {
            ulonglong2 a = *(const ulonglong2*)&bufA[kk*68 + ty*4];
            float4 bw = *(const float4*)&bufB[kk*68 + tx*4];
            ull b0 = dup2(bw.x), b1 = dup2(bw.y), b2 = dup2(bw.z), b3 = dup2(bw.w);
            fma2(o2[0][0], a.x, b0); fma2(o2[0][1], a.x, b1);
            fma2(o2[0][2], a.x, b2); fma2(o2[0][3], a.x, b3);
            fma2(o2[1][0], a.y, b0); fma2(o2[1][1], a.y, b1);
            fma2(o2[1][2], a.y, b2); fma2(o2[1][3], a.y, b3);
        }
        if (t == 2) {
            float2 u[2][4];
#pragma unroll
            for (int p = 0; p < 2; p++)
#pragma unroll
                for (int c = 0; c < 4; c++) u[p][c] = unpk(o2[p][c]);
            float4 bias = *(const float4*)&bs[2][tx*4];
#pragma unroll
            for (int r = 0; r < 4; r++) {
                float4 v4;
                float2* up = u[r >> 1];
                if (r & 1) v4 = make_float4(up[0].y + bias.x, up[1].y + bias.y, up[2].y + bias.z, up[3].y + bias.w);
                else       v4 = make_float4(up[0].x + bias.x, up[1].x + bias.y, up[2].x + bias.z, up[3].x + bias.w);
                *(float4*)&g_v[(row0 + ty*4 + r)*DD + tx*4] = v4;
            }
        } else {
            float* dst = (t == 0) ? g_qT : g_kT;
#pragma unroll
            for (int c = 0; c < 4; c++) {
                float2 p0 = unpk(o2[0][c]), p1 = unpk(o2[1][c]);
                float bias = bs[t][tx*4 + c];
                float4 v4 = {p0.x + bias, p0.y + bias, p1.x + bias, p1.y + bias};
                *(float4*)&dst[b*DD*NN + (tx*4 + c)*NN + n0 + ty*4] = v4;
            }
        }
        __syncthreads();
    }
}

// ============================================================
// Kernel 2: fused single-pass attention + FFN + LN + head.
// 512 threads. Per-chunk S (2 x 256 keys), exp fused into QK
// epilogue, row sums in registers, 1/sum applied in PV epilogue.
// ============================================================
#define SCH 260                  /* chunk S stride */
#define KV_OFF   16640
#define QT_OFF   33280
#define REL_OFF  37632
#define RK_OFF   37696
#define WS_OFF   38208           /* warpsum 128 */
#define INV_OFF  38336           /* 64 */
#define SMEM_FLOATS 38400
#define SMEM_BYTES  (SMEM_FLOATS*4)

__global__ __launch_bounds__(512) void attn_kernel(
    const int* __restrict__ ranks,
    const float* __restrict__ Wf1, const float* __restrict__ bf1,
    const float* __restrict__ Wf2, const float* __restrict__ bf2,
    const float* __restrict__ ln_g, const float* __restrict__ ln_b,
    const float* __restrict__ Ws1, const float* __restrict__ bs1,
    const float* __restrict__ Ws2, const float* __restrict__ bs2,
    float* __restrict__ out) {
    extern __shared__ float sm[];
    float* S    = sm;                    // 64 x 260 chunk (also FFN scratch)
    float* KV   = sm + KV_OFF;           // kT chunk / v chunk / aoT+w1 / w2 / ws
    float* qT   = sm + QT_OFF;           // 64 x 68 (later hnT)
    float* rel  = sm + REL_OFF;
    int*   rk   = (int*)(sm + RK_OFF);
    float* wsum = sm + WS_OFF;
    float* invs = sm + INV_OFF;

    const int tid = threadIdx.x;
    const int b = blockIdx.y;
    const int q0 = blockIdx.x * 64;
    const int base = b * NN;
    const int bT = b * DD * NN;
    const int warp = tid >> 5, lane = tid & 31;

    if (tid <= MAXDIST) rel[tid] = g_rel[tid];
    for (int m = tid; m < NN; m += 512) rk[m] = ranks[base + m];
#pragma unroll
    for (int j = 0; j < 2; j++) {
        int idx = tid + j*512;
        int d = idx >> 4, f = idx & 15;
        *(float4*)&qT[d*68 + f*4] = *(const float4*)&g_qT[bT + d*NN + q0 + f*4];
    }
    __syncthreads();

    // thread mapping for QK phase
    const int ty = tid >> 6;        // 8 rows each
    const int tx = tid & 63;        // 4 keys each
    int ri[8];
#pragma unroll
    for (int rr = 0; rr < 8; rr++) ri[rr] = rk[q0 + ty*8 + rr];
    // thread mapping for PV phase
    const int g3   = tid >> 7;
    const int t3   = tid & 127;
    const int rowg = t3 >> 3;
    const int colg = t3 & 7;

    float rs[8];
#pragma unroll
    for (int r = 0; r < 8; r++) rs[r] = 0.f;
    ull accpv[4][4];
#pragma unroll
    for (int r = 0; r < 4; r++)
#pragma unroll
        for (int c = 0; c < 4; c++) accpv[r][c] = 0ULL;

    for (int ch = 0; ch < 2; ch++) {
        const int k0 = ch * 256;
        // ---- stage kT chunk [64][260] ----
#pragma unroll
        for (int j = 0; j < 8; j++) {
            int idx = tid + j*512;
            int d = idx >> 6, f = idx & 63;
            *(float4*)&KV[d*SCH + f*4] = *(const float4*)&g_kT[bT + d*NN + k0 + f*4];
        }
        __syncthreads();

        // ---- S = exp2(QK^T * rel8l2), rowsums in registers ----
        {
            ull acc2[4][4];
#pragma unroll
            for (int p = 0; p < 4; p++)
#pragma unroll
                for (int c = 0; c < 4; c++) acc2[p][c] = 0ULL;
#pragma unroll 4
            for (int d = 0; d < 64; d++) {
                ulonglong2 a01 = *(const ulonglong2*)&qT[d*68 + ty*8];
                ulonglong2 a23 = *(const ulonglong2*)&qT[d*68 + ty*8 + 4];
                float4 kb = *(const float4*)&KV[d*SCH + tx*4];
                ull b0 = dup2(kb.x), b1 = dup2(kb.y), b2 = dup2(kb.z), b3 = dup2(kb.w);
                fma2(acc2[0][0], a01.x, b0); fma2(acc2[0][1], a01.x, b1);
                fma2(acc2[0][2], a01.x, b2); fma2(acc2[0][3], a01.x, b3);
                fma2(acc2[1][0], a01.y, b0); fma2(acc2[1][1], a01.y, b1);
                fma2(acc2[1][2], a01.y, b2); fma2(acc2[1][3], a01.y, b3);
                fma2(acc2[2][0], a23.x, b0); fma2(acc2[2][1], a23.x, b1);
                fma2(acc2[2][2], a23.x, b2); fma2(acc2[2][3], a23.x, b3);
                fma2(acc2[3][0], a23.y, b0); fma2(acc2[3][1], a23.y, b1);
                fma2(acc2[3][2], a23.y, b2); fma2(acc2[3][3], a23.y, b3);
            }
            int rkc[4];
#pragma unroll
            for (int c = 0; c < 4; c++) rkc[c] = rk[k0 + tx*4 + c];
#pragma unroll
            for (int p = 0; p < 4; p++) {
                float4 olo, ohi;
                float* plo = (float*)&olo;
                float* phi = (float*)&ohi;
                int rlo = ri[2*p], rhi = ri[2*p + 1];
#pragma unroll
                for (int c = 0; c < 4; c++) {
                    float2 u = unpk(acc2[p][c]);
                    int d0 = rlo - rkc[c]; if (d0 < 0) d0 = -d0; if (d0 > MAXDIST) d0 = MAXDIST;
                    int d1 = rhi - rkc[c]; if (d1 < 0) d1 = -d1; if (d1 > MAXDIST) d1 = MAXDIST;
                    float e0 = ex2(u.x * rel[d0]);
                    float e1 = ex2(u.y * rel[d1]);
                    plo[c] = e0; phi[c] = e1;
                    rs[2*p]     += e0;
                    rs[2*p + 1] += e1;
                }
                *(float4*)&S[(ty*8 + 2*p    )*SCH + tx*4] = olo;
                *(float4*)&S[(ty*8 + 2*p + 1)*SCH + tx*4] = ohi;
            }
        }
        if (ch == 1) {
            // finalize rowsums: warp-reduce, lane 0 writes per-warp sums
#pragma unroll
            for (int r = 0; r < 8; r++) {
                float v = rs[r];
#pragma unroll
                for (int o = 16; o >= 1; o >>= 1) v += __shfl_xor_sync(0xffffffffu, v, o);
                if (lane == 0) wsum[warp*8 + r] = v;
            }
        }
        __syncthreads();

        // ---- stage v chunk [256][64]; compute invs on second pass ----
#pragma unroll
        for (int j = 0; j < 8; j++) {
            int idx = tid + j*512;
            int key = idx >> 4, f = idx & 15;
            *(float4*)&KV[key*64 + f*4] = *(const float4*)&g_v[(base + k0 + key)*DD + f*4];
        }
        if (ch == 1 && tid < 64) {
            int tty = tid >> 3, r = tid & 7;
            invs[tid] = 1.f / (wsum[tty*16 + r] + wsum[tty*16 + 8 + r]);
        }
        __syncthreads();

        // ---- PV: splitK 4 groups x 64 keys of this chunk ----
        {
            const int kl0 = g3 * 64;
#pragma unroll 2
            for (int kl = 0; kl < 64; kl += 4) {
                float4 p0 = *(const float4*)&S[(rowg*4 + 0)*SCH + kl0 + kl];
                float4 p1 = *(const float4*)&S[(rowg*4 + 1)*SCH + kl0 + kl];
                float4 p2 = *(const float4*)&S[(rowg*4 + 2)*SCH + kl0 + kl];
                float4 p3 = *(const float4*)&S[(rowg*4 + 3)*SCH + kl0 + kl];
                const float* pp0 = (const float*)&p0;
                const float* pp1 = (const float*)&p1;
                const float* pp2 = (const float*)&p2;
                const float* pp3 = (const float*)&p3;
#pragma unroll
                for (int j = 0; j < 4; j++) {
                    ulonglong2 v0 = *(const ulonglong2*)&KV[(kl0 + kl + j)*64 + colg*8];
                    ulonglong2 v1 = *(const ulonglong2*)&KV[(kl0 + kl + j)*64 + colg*8 + 4];
                    ull pa0 = dup2(pp0[j]);
                    ull pa1 = dup2(pp1[j]);
                    ull pa2 = dup2(pp2[j]);
                    ull pa3 = dup2(pp3[j]);
                    fma2(accpv[0][0], pa0, v0.x); fma2(accpv[0][1], pa0, v0.y);
                    fma2(accpv[0][2], pa0, v1.x); fma2(accpv[0][3], pa0, v1.y);
                    fma2(accpv[1][0], pa1, v0.x); fma2(accpv[1][1], pa1, v0.y);
                    fma2(accpv[1][2], pa1, v1.x); fma2(accpv[1][3], pa1, v1.y);
                    fma2(accpv[2][0], pa2, v0.x); fma2(accpv[2][1], pa2, v0.y);
                    fma2(accpv[2][2], pa2, v1.x); fma2(accpv[2][3], pa2, v1.y);
                    fma2(accpv[3][0], pa3, v0.x); fma2(accpv[3][1], pa3, v0.y);
                    fma2(accpv[3][2], pa3, v1.x); fma2(accpv[3][3], pa3, v1.y);
                }
            }
        }
        __syncthreads();
    }

    // ---- splitK reduce + 1/sum + aoT ----
    {
        float po[4][8];
#pragma unroll
        for (int r = 0; r < 4; r++)
#pragma unroll
            for (int c = 0; c < 4; c++) {
                float2 u = unpk(accpv[r][c]);
                po[r][2*c] = u.x; po[r][2*c + 1] = u.y;
            }
        if (g3 > 0) {
            float* part = S + (g3 - 1)*4096;
#pragma unroll
            for (int r = 0; r < 4; r++) {
                *(float4*)&part[(rowg*4 + r)*64 + colg*8]     = *(float4*)&po[r][0];
                *(float4*)&part[(rowg*4 + r)*64 + colg*8 + 4] = *(float4*)&po[r][4];
            }
        }
        __syncthreads();
        if (g3 == 0) {
#pragma unroll
            for (int gg = 0; gg < 3; gg++) {
                float* part = S + gg*4096;
#pragma unroll
                for (int r = 0; r < 4; r++) {
                    float4 q0v = *(const float4*)&part[(rowg*4 + r)*64 + colg*8];
                    float4 q1v = *(const float4*)&part[(rowg*4 + r)*64 + colg*8 + 4];
                    po[r][0] += q0v.x; po[r][1] += q0v.y; po[r][2] += q0v.z; po[r][3] += q0v.w;
                    po[r][4] += q1v.x; po[r][5] += q1v.y; po[r][6] += q1v.z; po[r][7] += q1v.w;
                }
            }
            float iv[4];
#pragma unroll
            for (int r = 0; r < 4; r++) iv[r] = invs[rowg*4 + r];
#pragma unroll
            for (int c = 0; c < 8; c++) {
                float4 v4 = {po[0][c]*iv[0], po[1][c]*iv[1], po[2][c]*iv[2], po[3][c]*iv[3]};
                *(float4*)&KV[(colg*8 + c)*68 + rowg*4] = v4;
            }
        } else {
            float* w1 = KV + 4352;
            for (int j = (g3 - 1)*128 + t3; j < 2048; j += 384)
                *(float4*)&w1[j*4] = *(const float4*)&Wf1[j*4];
        }
    }
    __syncthreads();

    // ---- Phase 4a: h1 = relu(ao@Wf1+bf1) (64x128) ----
    {
        const float* w1 = KV + 4352;
        const int ty4 = tid >> 5, tx4 = tid & 31;
        ull acc2[2][4];
#pragma unroll
        for (int p = 0; p < 2; p++)
#pragma unroll
            for (int c = 0; c < 4; c++) acc2[p][c] = 0ULL;
#pragma unroll 4
        for (int kk = 0; kk < 64; kk++) {
            ulonglong2 a = *(const ulonglong2*)&KV[kk*68 + ty4*4];
            float4 bw = *(const float4*)&w1[kk*128 + tx4*4];
            ull b0 = dup2(bw.x), b1 = dup2(bw.y), b2 = dup2(bw.z), b3 = dup2(bw.w);
            fma2(acc2[0][0], a.x, b0); fma2(acc2[0][1], a.x, b1);
            fma2(acc2[0][2], a.x, b2); fma2(acc2[0][3], a.x, b3);
            fma2(acc2[1][0], a.y, b0); fma2(acc2[1][1], a.y, b1);
            fma2(acc2[1][2], a.y, b2); fma2(acc2[1][3], a.y, b3);
        }
        __syncthreads();
#pragma unroll
        for (int c = 0; c < 4; c++) {
            float bias = bf1[tx4*4 + c];
            float2 u0 = unpk(acc2[0][c]), u1 = unpk(acc2[1][c]);
            float4 v4 = {fmaxf(u0.x + bias, 0.f), fmaxf(u0.y + bias, 0.f),
                         fmaxf(u1.x + bias, 0.f), fmaxf(u1.y + bias, 0.f)};
            *(float4*)&S[(tx4*4 + c)*68 + ty4*4] = v4;
        }
#pragma unroll
        for (int j = 0; j < 4; j++) {
            int f = tid + j*512;
            *(float4*)&KV[f*4] = *(const float4*)&Wf2[f*4];
        }
    }
    __syncthreads();

    // ---- Phase 4b: h2 = h1@Wf2+bf2, LayerNorm ----
    {
        const int ty4 = tid >> 5, tx4 = tid & 31;
        ull acc2[2][2];
        acc2[0][0] = acc2[0][1] = acc2[1][0] = acc2[1][1] = 0ULL;
#pragma unroll 4
        for (int kk = 0; kk < 128; kk++) {
            ulonglong2 a = *(const ulonglong2*)&S[kk*68 + ty4*4];
            float2 bw = *(const float2*)&KV[kk*64 + tx4*2];
            ull b0 = dup2(bw.x), b1 = dup2(bw.y);
            fma2(acc2[0][0], a.x, b0); fma2(acc2[0][1], a.x, b1);
            fma2(acc2[1][0], a.y, b0); fma2(acc2[1][1], a.y, b1);
        }
        __syncthreads();
        float h2[4][2];
        {
            float2 u00 = unpk(acc2[0][0]), u01 = unpk(acc2[0][1]);
            float2 u10 = unpk(acc2[1][0]), u11 = unpk(acc2[1][1]);
            h2[0][0] = u00.x; h2[0][1] = u01.x;
            h2[1][0] = u00.y; h2[1][1] = u01.y;
            h2[2][0] = u10.x; h2[2][1] = u11.x;
            h2[3][0] = u10.y; h2[3][1] = u11.y;
        }
        float b0 = bf2[tx4*2], b1 = bf2[tx4*2 + 1];
        float g0v = ln_g[tx4*2], g1v = ln_g[tx4*2 + 1];
        float be0 = ln_b[tx4*2], be1 = ln_b[tx4*2 + 1];
#pragma unroll
        for (int r = 0; r < 4; r++) {
            float e0 = h2[r][0] + b0, e1 = h2[r][1] + b1;
            float s  = e0 + e1;
            float s2 = e0*e0 + e1*e1;
#pragma unroll
            for (int o = 16; o >= 1; o >>= 1) {
                s  += __shfl_xor_sync(0xffffffffu, s,  o);
                s2 += __shfl_xor_sync(0xffffffffu, s2, o);
            }
            float mu = s * (1.f/64.f);
            float var = s2 * (1.f/64.f) - mu*mu;
            float inv = rsqrtf(var + 1e-5f);
            qT[(tx4*2 + 0)*68 + ty4*4 + r] = (e0 - mu)*inv*g0v + be0;   // hnT
            qT[(tx4*2 + 1)*68 + ty4*4 + r] = (e1 - mu)*inv*g1v + be1;
        }
    }
    {
        *(float4*)&KV[tid*4] = *(const float4*)&Ws1[tid*4];
        if (tid < 8) *(float4*)&KV[2048 + tid*4] = *(const float4*)&Ws2[tid*4];
    }
    __syncthreads();

    // ---- Phase 4c: head (threads 0..255) ----
    if (tid < 256) {
        const int ty4 = tid >> 4, tx4 = tid & 15;
        float s1[4][2];
#pragma unroll
        for (int r = 0; r < 4; r++) { s1[r][0] = 0.f; s1[r][1] = 0.f; }
#pragma unroll 4
        for (int kk = 0; kk < 64; kk++) {
            float4 a = *(const float4*)&qT[kk*68 + ty4*4];
            float w0 = KV[kk*32 + tx4*2], w1b = KV[kk*32 + tx4*2 + 1];
            s1[0][0] = fmaf(a.x, w0, s1[0][0]); s1[0][1] = fmaf(a.x, w1b, s1[0][1]);
            s1[1][0] = fmaf(a.y, w0, s1[1][0]); s1[1][1] = fmaf(a.y, w1b, s1[1][1]);
            s1[2][0] = fmaf(a.z, w0, s1[2][0]); s1[2][1] = fmaf(a.z, w1b, s1[2][1]);
            s1[3][0] = fmaf(a.w, w0, s1[3][0]); s1[3][1] = fmaf(a.w, w1b, s1[3][1]);
        }
        float w2a = KV[2048 + tx4*2], w2b = KV[2048 + tx4*2 + 1];
        float ba = bs1[tx4*2], bb = bs1[tx4*2 + 1];
        float bs2v = bs2[0];
#pragma unroll
        for (int r = 0; r < 4; r++) {
            float pa = fmaxf(s1[r][0] + ba, 0.f);
            float pb = fmaxf(s1[r][1] + bb, 0.f);
            float p = pa*w2a + pb*w2b;
#pragma unroll
            for (int o = 8; o >= 1; o >>= 1) p += __shfl_xor_sync(0xffffffffu, p, o, 16);
            if (tx4 == 0) {
                float z = p + bs2v;
                out[base + q0 + ty4*4 + r] = 1.f / (1.f + __expf(-z));
            }
        }
    }
}

// ============================================================
extern "C" void kernel_launch(void* const* d_in, const int* in_sizes, int n_in,
                              void* d_out, int out_size) {
    const float* x     = (const float*)d_in[0];
    const int*   ranks = (const int*)  d_in[1];
    const float* Wp    = (const float*)d_in[2];
    const float* bp    = (const float*)d_in[3];
    const float* Wq    = (const float*)d_in[4];
    const float* bq    = (const float*)d_in[5];
    const float* Wk    = (const float*)d_in[6];
    const float* bk    = (const float*)d_in[7];
    const float* Wv    = (const float*)d_in[8];
    const float* bv    = (const float*)d_in[9];
    const float* Eemb  = (const float*)d_in[10];
    const float* Wr1   = (const float*)d_in[11];
    const float* br1   = (const float*)d_in[12];
    const float* Wr2   = (const float*)d_in[13];
    const float* Wf1   = (const float*)d_in[14];
    const float* bf1   = (const float*)d_in[15];
    const float* Wf2   = (const float*)d_in[16];
    const float* bf2   = (const float*)d_in[17];
    const float* ln_g  = (const float*)d_in[18];
    const float* ln_b  = (const float*)d_in[19];
    const float* Ws1   = (const float*)d_in[20];
    const float* bs1   = (const float*)d_in[21];
    const float* Ws2   = (const float*)d_in[22];
    const float* bs2   = (const float*)d_in[23];
    float* out = (float*)d_out;

    cudaFuncSetAttribute(attn_kernel, cudaFuncAttributeMaxDynamicSharedMemorySize, SMEM_BYTES);

    qkv_kernel<<<BB*NN/64, 256>>>(x, Wp, bp, Wq, bq, Wk, bk, Wv, bv,
                                  Eemb, Wr1, br1, Wr2);
    dim3 grid(NN/64, BB);
    attn_kernel<<<grid, 512, SMEM_BYTES>>>(ranks, Wf1, bf1, Wf2, bf2,
                                           ln_g, ln_b, Ws1, bs1, Ws2, bs2, out);
}